// round 2
// baseline (speedup 1.0000x reference)
#include <cuda_runtime.h>
#include <cstdint>

// ---------------------------------------------------------------------------
// GCN_8796093022507: 2-layer GCN, dropout 0.6, N=100000, E=6.4M.
// Both layers reduce to SCALAR edge scatter-adds (C_in=1 / C_out=1 rank-1 trick).
// Edge dtype (int32 vs int64) detected on-device: jnp.int64 request is usually
// silently downcast to int32 when jax_enable_x64=False.
// PRNG: JAX threefry2x32, partitionable mode.
// ---------------------------------------------------------------------------

#define NMAX 100000

__device__ int      g_deg[NMAX];
__device__ float    g_dinv[NMAX];
__device__ float    g_h0[NMAX];
__device__ float    g_s1[NMAX];
__device__ float    g_t[NMAX];
__device__ unsigned g_key[4];
__device__ int      g_is64;

__device__ __forceinline__ uint2 tf2x32(unsigned k0, unsigned k1,
                                        unsigned x0, unsigned x1) {
  unsigned k2 = k0 ^ k1 ^ 0x1BD11BDAu;
  x0 += k0; x1 += k1;
#define TFR(r) { x0 += x1; x1 = (x1 << (r)) | (x1 >> (32 - (r))); x1 ^= x0; }
  TFR(13) TFR(15) TFR(26) TFR(6)
  x0 += k1; x1 += k2 + 1u;
  TFR(17) TFR(29) TFR(16) TFR(24)
  x0 += k2; x1 += k0 + 2u;
  TFR(13) TFR(15) TFR(26) TFR(6)
  x0 += k0; x1 += k1 + 3u;
  TFR(17) TFR(29) TFR(16) TFR(24)
  x0 += k1; x1 += k2 + 4u;
  TFR(13) TFR(15) TFR(26) TFR(6)
  x0 += k2; x1 += k0 + 5u;
#undef TFR
  return make_uint2(x0, x1);
}

__device__ __forceinline__ bool keep40(unsigned k0, unsigned k1, unsigned i) {
  uint2 z = tf2x32(k0, k1, 0u, i);
  unsigned bits = z.x ^ z.y;
  float u = __uint_as_float((bits >> 9) | 0x3F800000u) - 1.0f;
  return u < 0.4f;
}

// Fetch edge index e from src/dst row of edge_index given runtime dtype.
__device__ __forceinline__ int edge_idx(const void* ei, long long row_off,
                                        long long e, int is64) {
  if (is64) return (int)((const long long*)ei)[row_off + e];
  return ((const int*)ei)[row_off + e];
}

__global__ void k_init(const void* ei, int E, int N) {
  int i = blockIdx.x * blockDim.x + threadIdx.x;
  if (i < N) { g_deg[i] = 0; g_s1[i] = 0.0f; }
  if (i == 0) {
    // dtype detect: as int64, 4 consecutive values all in [0,N) => int64.
    const long long* p = (const long long*)ei;
    bool ok64 = true;
    for (int k = 0; k < 4; k++) {
      long long v = p[k];
      if (v < 0 || v >= (long long)N) ok64 = false;
    }
    g_is64 = ok64 ? 1 : 0;
    // jax.random.key(42); split -> partitionable: key_i = threefry(key,(0,i))
    uint2 ka = tf2x32(0u, 42u, 0u, 0u);
    uint2 kb = tf2x32(0u, 42u, 0u, 1u);
    g_key[0] = ka.x; g_key[1] = ka.y;
    g_key[2] = kb.x; g_key[3] = kb.y;
  }
}

__global__ void k_deg(const void* ei, int E, int N) {
  int i = blockIdx.x * blockDim.x + threadIdx.x;
  if (i >= E) return;
  int is64 = g_is64;
  int d = edge_idx(ei, E, i, is64);          // dst row starts at offset E
  if ((unsigned)d < (unsigned)N) atomicAdd(&g_deg[d], 1);
}

__global__ void k_node1(const float* __restrict__ x, const float* __restrict__ b2,
                        float* __restrict__ out, int N) {
  int i = blockIdx.x * blockDim.x + threadIdx.x;
  if (i >= N) return;
  int d = g_deg[i];
  g_dinv[i] = (d > 0) ? rsqrtf((float)d) : 0.0f;
  g_h0[i] = keep40(g_key[0], g_key[1], (unsigned)i) ? x[i] * 2.5f : 0.0f;
  out[i] = b2[0];
}

__global__ void k_edge1(const void* ei, int E, int N) {
  int i = blockIdx.x * blockDim.x + threadIdx.x;
  if (i >= E) return;
  int is64 = g_is64;
  int s = edge_idx(ei, 0, i, is64);
  int d = edge_idx(ei, E, i, is64);
  if ((unsigned)s >= (unsigned)N || (unsigned)d >= (unsigned)N) return;
  float v = g_h0[s] * (g_dinv[s] * g_dinv[d]);
  if (v != 0.0f) atomicAdd(&g_s1[d], v);
}

__global__ void k_node2(const float* __restrict__ W1, const float* __restrict__ b1,
                        const float* __restrict__ W2, int N) {
  int tid = blockIdx.x * blockDim.x + threadIdx.x;
  int n = tid >> 4, j = tid & 15;
  if (n >= N) return;
  float v = fmaxf(g_s1[n] * __ldg(&W1[j]) + __ldg(&b1[j]), 0.0f);
  unsigned i = (unsigned)n * 16u + (unsigned)j;
  v = keep40(g_key[2], g_key[3], i) ? v * 2.5f : 0.0f;
  v *= __ldg(&W2[j]);
  #pragma unroll
  for (int off = 8; off; off >>= 1)
    v += __shfl_xor_sync(0xFFFFFFFFu, v, off, 16);
  if (j == 0) g_t[n] = v;
}

__global__ void k_edge2(const void* ei, float* __restrict__ out, int E, int N) {
  int i = blockIdx.x * blockDim.x + threadIdx.x;
  if (i >= E) return;
  int is64 = g_is64;
  int s = edge_idx(ei, 0, i, is64);
  int d = edge_idx(ei, E, i, is64);
  if ((unsigned)s >= (unsigned)N || (unsigned)d >= (unsigned)N) return;
  float v = g_t[s] * (g_dinv[s] * g_dinv[d]);
  if (v != 0.0f) atomicAdd(&out[d], v);
}

extern "C" void kernel_launch(void* const* d_in, const int* in_sizes, int n_in,
                              void* d_out, int out_size) {
  const float* x  = (const float*)d_in[0];
  const void*  ei = d_in[1];
  const float* W1 = (const float*)d_in[2];
  const float* b1 = (const float*)d_in[3];
  const float* W2 = (const float*)d_in[4];
  const float* b2 = (const float*)d_in[5];
  float* out = (float*)d_out;

  int N = in_sizes[0];        // x is [N,1]
  int E = in_sizes[1] / 2;    // edge_index is [2,E]

  const int TB = 256;
  int nblkN   = (N + TB - 1) / TB;
  int nblkE   = (E + TB - 1) / TB;
  int nblkN16 = (N * 16 + TB - 1) / TB;

  k_init <<<nblkN,  TB>>>(ei, E, N);
  k_deg  <<<nblkE,  TB>>>(ei, E, N);
  k_node1<<<nblkN,  TB>>>(x, b2, out, N);
  k_edge1<<<nblkE,  TB>>>(ei, E, N);
  k_node2<<<nblkN16, TB>>>(W1, b1, W2, N);
  k_edge2<<<nblkE,  TB>>>(ei, out, E, N);
}

// round 3
// speedup vs baseline: 1.3733x; 1.3733x over previous
#include <cuda_runtime.h>
#include <cstdint>

// ---------------------------------------------------------------------------
// GCN_8796093022507: 2-layer GCN, dropout 0.6, N=100000, E=6.4M.
// R3: (a) factor dinv[d] out of the scatter => 1 gather + 1 atomic per edge,
//     (b) one-time int64->int32 edge decode fused with degree histogram,
//     (c) edge passes read int32 indices (half the stream traffic).
// PRNG: JAX threefry2x32, partitionable mode (verified R2, rel_err 2.9e-7).
// ---------------------------------------------------------------------------

#define NMAX 100000
#define EMAX 6400000

__device__ int      g_deg[NMAX];
__device__ float    g_dinv[NMAX];
__device__ float    g_u[NMAX];     // layer1: dropout(x)*dinv
__device__ float    g_w[NMAX];     // layer2: t*dinv
__device__ float    g_acc1[NMAX];  // sum of u[s] per dst
__device__ float    g_acc2[NMAX];  // sum of w[s] per dst
__device__ int      g_src32[EMAX];
__device__ int      g_dst32[EMAX];
__device__ unsigned g_key[4];
__device__ int      g_is64;

__device__ __forceinline__ uint2 tf2x32(unsigned k0, unsigned k1,
                                        unsigned x0, unsigned x1) {
  unsigned k2 = k0 ^ k1 ^ 0x1BD11BDAu;
  x0 += k0; x1 += k1;
#define TFR(r) { x0 += x1; x1 = (x1 << (r)) | (x1 >> (32 - (r))); x1 ^= x0; }
  TFR(13) TFR(15) TFR(26) TFR(6)
  x0 += k1; x1 += k2 + 1u;
  TFR(17) TFR(29) TFR(16) TFR(24)
  x0 += k2; x1 += k0 + 2u;
  TFR(13) TFR(15) TFR(26) TFR(6)
  x0 += k0; x1 += k1 + 3u;
  TFR(17) TFR(29) TFR(16) TFR(24)
  x0 += k1; x1 += k2 + 4u;
  TFR(13) TFR(15) TFR(26) TFR(6)
  x0 += k2; x1 += k0 + 5u;
#undef TFR
  return make_uint2(x0, x1);
}

__device__ __forceinline__ bool keep40(unsigned k0, unsigned k1, unsigned i) {
  uint2 z = tf2x32(k0, k1, 0u, i);
  unsigned bits = z.x ^ z.y;
  float u = __uint_as_float((bits >> 9) | 0x3F800000u) - 1.0f;
  return u < 0.4f;
}

__global__ void k_init(const void* ei, int E, int N) {
  int i = blockIdx.x * blockDim.x + threadIdx.x;
  if (i < N) { g_deg[i] = 0; g_acc1[i] = 0.0f; g_acc2[i] = 0.0f; }
  if (i == 0) {
    const long long* p = (const long long*)ei;
    bool ok64 = true;
    for (int k = 0; k < 4; k++) {
      long long v = p[k];
      if (v < 0 || v >= (long long)N) ok64 = false;
    }
    g_is64 = ok64 ? 1 : 0;
    uint2 ka = tf2x32(0u, 42u, 0u, 0u);
    uint2 kb = tf2x32(0u, 42u, 0u, 1u);
    g_key[0] = ka.x; g_key[1] = ka.y;
    g_key[2] = kb.x; g_key[3] = kb.y;
  }
}

// Decode edge_index to int32 scratch + in-degree histogram (dst row).
__global__ void k_decode_deg(const void* ei, int npairs, int E, int N) {
  int i = blockIdx.x * blockDim.x + threadIdx.x;
  if (i >= npairs) return;
  int is64 = g_is64;
  int e0 = 2 * i;
  int s0, s1v, d0, d1v;
  bool two = (e0 + 1 < E);
  if (is64) {
    const long long* p = (const long long*)ei;
    if (two) {
      longlong2 sv = ((const longlong2*)p)[i];
      longlong2 dv = ((const longlong2*)(p + E))[i];
      s0 = (int)sv.x; s1v = (int)sv.y; d0 = (int)dv.x; d1v = (int)dv.y;
    } else {
      s0 = (int)p[e0]; d0 = (int)p[E + e0]; s1v = 0; d1v = 0;
    }
  } else {
    const int* p = (const int*)ei;
    if (two) {
      int2 sv = ((const int2*)p)[i];
      int2 dv = ((const int2*)(p + E))[i];
      s0 = sv.x; s1v = sv.y; d0 = dv.x; d1v = dv.y;
    } else {
      s0 = p[e0]; d0 = p[E + e0]; s1v = 0; d1v = 0;
    }
  }
  if (two) {
    ((int2*)g_src32)[i] = make_int2(s0, s1v);
    ((int2*)g_dst32)[i] = make_int2(d0, d1v);
    if ((unsigned)d0 < (unsigned)N) atomicAdd(&g_deg[d0], 1);
    if ((unsigned)d1v < (unsigned)N) atomicAdd(&g_deg[d1v], 1);
  } else {
    g_src32[e0] = s0; g_dst32[e0] = d0;
    if ((unsigned)d0 < (unsigned)N) atomicAdd(&g_deg[d0], 1);
  }
}

__global__ void k_node1(const float* __restrict__ x, int N) {
  int i = blockIdx.x * blockDim.x + threadIdx.x;
  if (i >= N) return;
  int d = g_deg[i];
  float dinv = (d > 0) ? rsqrtf((float)d) : 0.0f;
  g_dinv[i] = dinv;
  // u = dropout1(x) * dinv  (scatter payload, dst-norm factored out)
  g_u[i] = keep40(g_key[0], g_key[1], (unsigned)i) ? x[i] * 2.5f * dinv : 0.0f;
}

__global__ void k_edge1(int E, int N) {
  int i = blockIdx.x * blockDim.x + threadIdx.x;
  if (i >= E) return;
  int s = g_src32[i];
  float v = g_u[s];
  if (v != 0.0f) atomicAdd(&g_acc1[g_dst32[i]], v);
}

__global__ void k_node2(const float* __restrict__ W1, const float* __restrict__ b1,
                        const float* __restrict__ W2, int N) {
  int tid = blockIdx.x * blockDim.x + threadIdx.x;
  int n = tid >> 4, j = tid & 15;
  if (n >= N) return;
  float dinv = g_dinv[n];
  float s1 = g_acc1[n] * dinv;                                     // finish layer1
  float v = fmaxf(s1 * __ldg(&W1[j]) + __ldg(&b1[j]), 0.0f);       // relu
  unsigned i = (unsigned)n * 16u + (unsigned)j;
  v = keep40(g_key[2], g_key[3], i) ? v * 2.5f : 0.0f;             // dropout2
  v *= __ldg(&W2[j]);
  #pragma unroll
  for (int off = 8; off; off >>= 1)
    v += __shfl_xor_sync(0xFFFFFFFFu, v, off, 16);
  if (j == 0) g_w[n] = v * dinv;                                   // w = t*dinv
}

__global__ void k_edge2(int E, int N) {
  int i = blockIdx.x * blockDim.x + threadIdx.x;
  if (i >= E) return;
  int s = g_src32[i];
  float v = g_w[s];
  if (v != 0.0f) atomicAdd(&g_acc2[g_dst32[i]], v);
}

__global__ void k_node3(const float* __restrict__ b2, float* __restrict__ out, int N) {
  int i = blockIdx.x * blockDim.x + threadIdx.x;
  if (i >= N) return;
  out[i] = g_acc2[i] * g_dinv[i] + b2[0];
}

extern "C" void kernel_launch(void* const* d_in, const int* in_sizes, int n_in,
                              void* d_out, int out_size) {
  const float* x  = (const float*)d_in[0];
  const void*  ei = d_in[1];
  const float* W1 = (const float*)d_in[2];
  const float* b1 = (const float*)d_in[3];
  const float* W2 = (const float*)d_in[4];
  const float* b2 = (const float*)d_in[5];
  float* out = (float*)d_out;

  int N = in_sizes[0];
  int E = in_sizes[1] / 2;

  const int TB = 256;
  int nblkN   = (N + TB - 1) / TB;
  int npairs  = (E + 1) / 2;
  int nblkP   = (npairs + TB - 1) / TB;
  int nblkE   = (E + TB - 1) / TB;
  int nblkN16 = (N * 16 + TB - 1) / TB;

  k_init      <<<nblkN,  TB>>>(ei, E, N);
  k_decode_deg<<<nblkP,  TB>>>(ei, npairs, E, N);
  k_node1     <<<nblkN,  TB>>>(x, N);
  k_edge1     <<<nblkE,  TB>>>(E, N);
  k_node2     <<<nblkN16, TB>>>(W1, b1, W2, N);
  k_edge2     <<<nblkE,  TB>>>(E, N);
  k_node3     <<<nblkN,  TB>>>(b2, out, N);
}

// round 4
// speedup vs baseline: 1.3790x; 1.0042x over previous
#include <cuda_runtime.h>
#include <cstdint>

// ---------------------------------------------------------------------------
// GCN_8796093022507: 2-layer GCN, dropout 0.6, N=100000, E=6.4M.
// R4: interleaved (src,dst) int2 edge list; edge kernels process 2 edges per
// thread via a single int4 load -> ~2x fewer LSU issues per edge (we are at
// the LSU/wavefront floor per R3 ncu: issue 10.6%, L2 61%, DRAM 16.5%).
// PRNG: JAX threefry2x32, partitionable (verified, rel_err ~3e-7).
// ---------------------------------------------------------------------------

#define NMAX 100000
#define EMAX 6400000

__device__ int      g_deg[NMAX];
__device__ float    g_dinv[NMAX];
__device__ float    g_u[NMAX];        // layer1 payload: dropout1(x)*dinv
__device__ float    g_w[NMAX];        // layer2 payload: t*dinv
__device__ float    g_acc1[NMAX];
__device__ float    g_acc2[NMAX];
__device__ int2     g_edge[EMAX + 1]; // interleaved (s,d)
__device__ unsigned g_key[4];
__device__ int      g_is64;

__device__ __forceinline__ uint2 tf2x32(unsigned k0, unsigned k1,
                                        unsigned x0, unsigned x1) {
  unsigned k2 = k0 ^ k1 ^ 0x1BD11BDAu;
  x0 += k0; x1 += k1;
#define TFR(r) { x0 += x1; x1 = (x1 << (r)) | (x1 >> (32 - (r))); x1 ^= x0; }
  TFR(13) TFR(15) TFR(26) TFR(6)
  x0 += k1; x1 += k2 + 1u;
  TFR(17) TFR(29) TFR(16) TFR(24)
  x0 += k2; x1 += k0 + 2u;
  TFR(13) TFR(15) TFR(26) TFR(6)
  x0 += k0; x1 += k1 + 3u;
  TFR(17) TFR(29) TFR(16) TFR(24)
  x0 += k1; x1 += k2 + 4u;
  TFR(13) TFR(15) TFR(26) TFR(6)
  x0 += k2; x1 += k0 + 5u;
#undef TFR
  return make_uint2(x0, x1);
}

__device__ __forceinline__ bool keep40(unsigned k0, unsigned k1, unsigned i) {
  uint2 z = tf2x32(k0, k1, 0u, i);
  unsigned bits = z.x ^ z.y;
  float u = __uint_as_float((bits >> 9) | 0x3F800000u) - 1.0f;
  return u < 0.4f;
}

__global__ void k_init(const void* ei, int E, int N) {
  int i = blockIdx.x * blockDim.x + threadIdx.x;
  if (i < N) { g_deg[i] = 0; g_acc1[i] = 0.0f; g_acc2[i] = 0.0f; }
  if (i == 0) {
    const long long* p = (const long long*)ei;
    bool ok64 = true;
    for (int k = 0; k < 4; k++) {
      long long v = p[k];
      if (v < 0 || v >= (long long)N) ok64 = false;
    }
    g_is64 = ok64 ? 1 : 0;
    uint2 ka = tf2x32(0u, 42u, 0u, 0u);
    uint2 kb = tf2x32(0u, 42u, 0u, 1u);
    g_key[0] = ka.x; g_key[1] = ka.y;
    g_key[2] = kb.x; g_key[3] = kb.y;
  }
}

// Decode edge_index -> interleaved (s,d) int2 pairs + in-degree histogram.
__global__ void k_decode_deg(const void* ei, int npairs, int E, int N) {
  int i = blockIdx.x * blockDim.x + threadIdx.x;
  if (i >= npairs) return;
  int is64 = g_is64;
  int e0 = 2 * i;
  bool two = (e0 + 1 < E);
  int s0, s1v, d0, d1v;
  if (is64) {
    const long long* p = (const long long*)ei;
    if (two) {
      longlong2 sv = ((const longlong2*)p)[i];
      longlong2 dv = ((const longlong2*)(p + E))[i];
      s0 = (int)sv.x; s1v = (int)sv.y; d0 = (int)dv.x; d1v = (int)dv.y;
    } else {
      s0 = (int)p[e0]; d0 = (int)p[E + e0]; s1v = 0; d1v = 0;
    }
  } else {
    const int* p = (const int*)ei;
    if (two) {
      int2 sv = ((const int2*)p)[i];
      int2 dv = ((const int2*)(p + E))[i];
      s0 = sv.x; s1v = sv.y; d0 = dv.x; d1v = dv.y;
    } else {
      s0 = p[e0]; d0 = p[E + e0]; s1v = 0; d1v = 0;
    }
  }
  ((int4*)g_edge)[i] = make_int4(s0, d0, s1v, d1v);
  if ((unsigned)d0 < (unsigned)N) atomicAdd(&g_deg[d0], 1);
  if (two && (unsigned)d1v < (unsigned)N) atomicAdd(&g_deg[d1v], 1);
}

__global__ void k_node1(const float* __restrict__ x, int N) {
  int i = blockIdx.x * blockDim.x + threadIdx.x;
  if (i >= N) return;
  int d = g_deg[i];
  float dinv = (d > 0) ? rsqrtf((float)d) : 0.0f;
  g_dinv[i] = dinv;
  g_u[i] = keep40(g_key[0], g_key[1], (unsigned)i) ? x[i] * 2.5f * dinv : 0.0f;
}

__global__ void k_edge1(int npairs, int E) {
  int i = blockIdx.x * blockDim.x + threadIdx.x;
  if (i >= npairs) return;
  int4 e = ((const int4*)g_edge)[i];     // (s0,d0,s1,d1)
  float v0 = g_u[e.x];
  if (v0 != 0.0f) atomicAdd(&g_acc1[e.y], v0);
  if (2 * i + 1 < E) {
    float v1 = g_u[e.z];
    if (v1 != 0.0f) atomicAdd(&g_acc1[e.w], v1);
  }
}

__global__ void k_node2(const float* __restrict__ W1, const float* __restrict__ b1,
                        const float* __restrict__ W2, int N) {
  int tid = blockIdx.x * blockDim.x + threadIdx.x;
  int n = tid >> 4, j = tid & 15;
  if (n >= N) return;
  float dinv = g_dinv[n];
  float s1 = g_acc1[n] * dinv;                                 // finish layer1
  float v = fmaxf(s1 * __ldg(&W1[j]) + __ldg(&b1[j]), 0.0f);   // relu
  unsigned i = (unsigned)n * 16u + (unsigned)j;
  v = keep40(g_key[2], g_key[3], i) ? v * 2.5f : 0.0f;         // dropout2
  v *= __ldg(&W2[j]);
  #pragma unroll
  for (int off = 8; off; off >>= 1)
    v += __shfl_xor_sync(0xFFFFFFFFu, v, off, 16);
  if (j == 0) g_w[n] = v * dinv;                               // payload = t*dinv
}

__global__ void k_edge2(int npairs, int E) {
  int i = blockIdx.x * blockDim.x + threadIdx.x;
  if (i >= npairs) return;
  int4 e = ((const int4*)g_edge)[i];
  float v0 = g_w[e.x];
  if (v0 != 0.0f) atomicAdd(&g_acc2[e.y], v0);
  if (2 * i + 1 < E) {
    float v1 = g_w[e.z];
    if (v1 != 0.0f) atomicAdd(&g_acc2[e.w], v1);
  }
}

__global__ void k_node3(const float* __restrict__ b2, float* __restrict__ out, int N) {
  int i = blockIdx.x * blockDim.x + threadIdx.x;
  if (i >= N) return;
  out[i] = g_acc2[i] * g_dinv[i] + b2[0];
}

extern "C" void kernel_launch(void* const* d_in, const int* in_sizes, int n_in,
                              void* d_out, int out_size) {
  const float* x  = (const float*)d_in[0];
  const void*  ei = d_in[1];
  const float* W1 = (const float*)d_in[2];
  const float* b1 = (const float*)d_in[3];
  const float* W2 = (const float*)d_in[4];
  const float* b2 = (const float*)d_in[5];
  float* out = (float*)d_out;

  int N = in_sizes[0];
  int E = in_sizes[1] / 2;

  const int TB = 256;
  int nblkN   = (N + TB - 1) / TB;
  int npairs  = (E + 1) / 2;
  int nblkP   = (npairs + TB - 1) / TB;
  int nblkN16 = (N * 16 + TB - 1) / TB;

  k_init      <<<nblkN,  TB>>>(ei, E, N);
  k_decode_deg<<<nblkP,  TB>>>(ei, npairs, E, N);
  k_node1     <<<nblkN,  TB>>>(x, N);
  k_edge1     <<<nblkP,  TB>>>(npairs, E);
  k_node2     <<<nblkN16, TB>>>(W1, b1, W2, N);
  k_edge2     <<<nblkP,  TB>>>(npairs, E);
  k_node3     <<<nblkN,  TB>>>(b2, out, N);
}

// round 5
// speedup vs baseline: 1.6833x; 1.2206x over previous
#include <cuda_runtime.h>
#include <cuda_fp16.h>
#include <cstdint>

// ---------------------------------------------------------------------------
// GCN_8796093022507: 2-layer GCN, dropout 0.6, N=100000, E=6.4M.
// R5: (a) fp16 payload tables (200KB -> L1-resident gathers, halves random L2
//     sector traffic), (b) decode pass removed (input is int32; reading raw
//     rows is byte-identical), deg-only histogram pass with int4 loads.
// PRNG: JAX threefry2x32, partitionable (verified, rel_err ~3e-7 in fp32).
// ---------------------------------------------------------------------------

#define NMAX 100000

__device__ int      g_deg[NMAX];
__device__ float    g_dinv[NMAX];
__device__ __half   g_u[NMAX];     // layer1 payload: dropout1(x)*dinv (fp16)
__device__ __half   g_w[NMAX];     // layer2 payload: t*dinv (fp16)
__device__ float    g_acc1[NMAX];
__device__ float    g_acc2[NMAX];
__device__ unsigned g_key[4];
__device__ int      g_is64;

__device__ __forceinline__ uint2 tf2x32(unsigned k0, unsigned k1,
                                        unsigned x0, unsigned x1) {
  unsigned k2 = k0 ^ k1 ^ 0x1BD11BDAu;
  x0 += k0; x1 += k1;
#define TFR(r) { x0 += x1; x1 = (x1 << (r)) | (x1 >> (32 - (r))); x1 ^= x0; }
  TFR(13) TFR(15) TFR(26) TFR(6)
  x0 += k1; x1 += k2 + 1u;
  TFR(17) TFR(29) TFR(16) TFR(24)
  x0 += k2; x1 += k0 + 2u;
  TFR(13) TFR(15) TFR(26) TFR(6)
  x0 += k0; x1 += k1 + 3u;
  TFR(17) TFR(29) TFR(16) TFR(24)
  x0 += k1; x1 += k2 + 4u;
  TFR(13) TFR(15) TFR(26) TFR(6)
  x0 += k2; x1 += k0 + 5u;
#undef TFR
  return make_uint2(x0, x1);
}

__device__ __forceinline__ bool keep40(unsigned k0, unsigned k1, unsigned i) {
  uint2 z = tf2x32(k0, k1, 0u, i);
  unsigned bits = z.x ^ z.y;
  float u = __uint_as_float((bits >> 9) | 0x3F800000u) - 1.0f;
  return u < 0.4f;
}

__global__ void k_init(const void* ei, int E, int N) {
  int i = blockIdx.x * blockDim.x + threadIdx.x;
  if (i < N) { g_deg[i] = 0; g_acc1[i] = 0.0f; g_acc2[i] = 0.0f; }
  if (i == 0) {
    const long long* p = (const long long*)ei;
    bool ok64 = true;
    for (int k = 0; k < 4; k++) {
      long long v = p[k];
      if (v < 0 || v >= (long long)N) ok64 = false;
    }
    g_is64 = ok64 ? 1 : 0;
    uint2 ka = tf2x32(0u, 42u, 0u, 0u);
    uint2 kb = tf2x32(0u, 42u, 0u, 1u);
    g_key[0] = ka.x; g_key[1] = ka.y;
    g_key[2] = kb.x; g_key[3] = kb.y;
  }
}

// In-degree histogram over the dst row, 4 edges per thread.
__global__ void k_deg(const void* ei, int nquads, int E, int N) {
  int i = blockIdx.x * blockDim.x + threadIdx.x;
  if (i >= nquads) return;
  int e0 = 4 * i;
  if (g_is64) {
    const long long* dstr = (const long long*)ei + E;
    #pragma unroll
    for (int k = 0; k < 4; k++) {
      if (e0 + k < E) {
        int d = (int)dstr[e0 + k];
        if ((unsigned)d < (unsigned)N) atomicAdd(&g_deg[d], 1);
      }
    }
  } else {
    const int* dstr = (const int*)ei + E;
    if (e0 + 3 < E) {
      int4 d4 = ((const int4*)dstr)[i];
      atomicAdd(&g_deg[d4.x], 1);
      atomicAdd(&g_deg[d4.y], 1);
      atomicAdd(&g_deg[d4.z], 1);
      atomicAdd(&g_deg[d4.w], 1);
    } else {
      for (int k = 0; k < 4 && e0 + k < E; k++)
        atomicAdd(&g_deg[dstr[e0 + k]], 1);
    }
  }
}

__global__ void k_node1(const float* __restrict__ x, int N) {
  int i = blockIdx.x * blockDim.x + threadIdx.x;
  if (i >= N) return;
  int d = g_deg[i];
  float dinv = (d > 0) ? rsqrtf((float)d) : 0.0f;
  g_dinv[i] = dinv;
  float u = keep40(g_key[0], g_key[1], (unsigned)i) ? x[i] * 2.5f * dinv : 0.0f;
  g_u[i] = __float2half(u);
}

// Scatter payload[src] into acc[dst]; 2 edges per thread, raw row reads.
__global__ void k_edge1(const void* ei, int npairs, int E) {
  int i = blockIdx.x * blockDim.x + threadIdx.x;
  if (i >= npairs) return;
  int e0 = 2 * i;
  bool two = (e0 + 1 < E);
  int s0, s1v, d0, d1v;
  if (g_is64) {
    const long long* p = (const long long*)ei;
    s0 = (int)p[e0]; d0 = (int)p[E + e0];
    s1v = two ? (int)p[e0 + 1] : 0; d1v = two ? (int)p[E + e0 + 1] : 0;
  } else {
    const int* p = (const int*)ei;
    int2 sv = ((const int2*)p)[i];
    int2 dv = ((const int2*)(p + E))[i];
    s0 = sv.x; s1v = sv.y; d0 = dv.x; d1v = dv.y;
  }
  float v0 = __half2float(g_u[s0]);
  if (v0 != 0.0f) atomicAdd(&g_acc1[d0], v0);
  if (two) {
    float v1 = __half2float(g_u[s1v]);
    if (v1 != 0.0f) atomicAdd(&g_acc1[d1v], v1);
  }
}

__global__ void k_node2(const float* __restrict__ W1, const float* __restrict__ b1,
                        const float* __restrict__ W2, int N) {
  int tid = blockIdx.x * blockDim.x + threadIdx.x;
  int n = tid >> 4, j = tid & 15;
  if (n >= N) return;
  float dinv = g_dinv[n];
  float s1 = g_acc1[n] * dinv;                                 // finish layer1
  float v = fmaxf(s1 * __ldg(&W1[j]) + __ldg(&b1[j]), 0.0f);   // relu
  unsigned i = (unsigned)n * 16u + (unsigned)j;
  v = keep40(g_key[2], g_key[3], i) ? v * 2.5f : 0.0f;         // dropout2
  v *= __ldg(&W2[j]);
  #pragma unroll
  for (int off = 8; off; off >>= 1)
    v += __shfl_xor_sync(0xFFFFFFFFu, v, off, 16);
  if (j == 0) g_w[n] = __float2half(v * dinv);                 // payload = t*dinv
}

__global__ void k_edge2(const void* ei, int npairs, int E) {
  int i = blockIdx.x * blockDim.x + threadIdx.x;
  if (i >= npairs) return;
  int e0 = 2 * i;
  bool two = (e0 + 1 < E);
  int s0, s1v, d0, d1v;
  if (g_is64) {
    const long long* p = (const long long*)ei;
    s0 = (int)p[e0]; d0 = (int)p[E + e0];
    s1v = two ? (int)p[e0 + 1] : 0; d1v = two ? (int)p[E + e0 + 1] : 0;
  } else {
    const int* p = (const int*)ei;
    int2 sv = ((const int2*)p)[i];
    int2 dv = ((const int2*)(p + E))[i];
    s0 = sv.x; s1v = sv.y; d0 = dv.x; d1v = dv.y;
  }
  float v0 = __half2float(g_w[s0]);
  if (v0 != 0.0f) atomicAdd(&g_acc2[d0], v0);
  if (two) {
    float v1 = __half2float(g_w[s1v]);
    if (v1 != 0.0f) atomicAdd(&g_acc2[d1v], v1);
  }
}

__global__ void k_node3(const float* __restrict__ b2, float* __restrict__ out, int N) {
  int i = blockIdx.x * blockDim.x + threadIdx.x;
  if (i >= N) return;
  out[i] = g_acc2[i] * g_dinv[i] + b2[0];
}

extern "C" void kernel_launch(void* const* d_in, const int* in_sizes, int n_in,
                              void* d_out, int out_size) {
  const float* x  = (const float*)d_in[0];
  const void*  ei = d_in[1];
  const float* W1 = (const float*)d_in[2];
  const float* b1 = (const float*)d_in[3];
  const float* W2 = (const float*)d_in[4];
  const float* b2 = (const float*)d_in[5];
  float* out = (float*)d_out;

  int N = in_sizes[0];
  int E = in_sizes[1] / 2;

  const int TB = 256;
  int nblkN   = (N + TB - 1) / TB;
  int npairs  = (E + 1) / 2;
  int nquads  = (E + 3) / 4;
  int nblkP   = (npairs + TB - 1) / TB;
  int nblkQ   = (nquads + TB - 1) / TB;
  int nblkN16 = (N * 16 + TB - 1) / TB;

  k_init <<<nblkN,  TB>>>(ei, E, N);
  k_deg  <<<nblkQ,  TB>>>(ei, nquads, E, N);
  k_node1<<<nblkN,  TB>>>(x, N);
  k_edge1<<<nblkP,  TB>>>(ei, npairs, E);
  k_node2<<<nblkN16, TB>>>(W1, b1, W2, N);
  k_edge2<<<nblkP,  TB>>>(ei, npairs, E);
  k_node3<<<nblkN,  TB>>>(b2, out, N);
}